// round 10
// baseline (speedup 1.0000x reference)
#include <cuda_runtime.h>
#include <cuda_fp16.h>
#include <math.h>
#include <cstdint>

// ---------------------------------------------------------------------------
// ChannelBlock on GB300 (compute_103 base target):
// fp16 mma.sync GEMMs, BK=64, 2-stage cp.async, 3 CTAs/SM via
// __launch_bounds__(256,3) + register-lean addressing.
// Shapes: B=8, H=W=64, N=4096, C=384, heads=8, d=48, Ch=1536, M=B*N=32768
// ---------------------------------------------------------------------------

#define BB     8
#define HH     64
#define WW     64
#define NT     4096
#define CC     384
#define NHEAD  8
#define DH     48
#define MROWS  (BB*NT)     // 32768
#define CHID   1536

// ---- scratch (static device arrays; no allocation allowed) ----------------
__device__ float g_xn [MROWS*CC];
__device__ float g_q  [MROWS*CC];
__device__ float g_kv [MROWS*2*CC];
__device__ float g_attn[BB*NHEAD*DH*DH];
__device__ float g_x2 [MROWS*CC];
__device__ float g_x3 [MROWS*CC];

__device__ __half g_xn_h[MROWS*CC];
__device__ __half g_sn_h[MROWS*CC];
__device__ __half g_ao_h[MROWS*CC];
__device__ __half g_h0_h[MROWS*CC];
__device__ __half g_h1_h[MROWS*CHID];

// weights, fp16, TRANSPOSED [N,K] layout (GEMM B operand)
__device__ __half g_wq_h [CC*CC];
__device__ __half g_wkv_h[2*CC*CC];
__device__ __half g_wpj_h[CC*CC];
__device__ __half g_wf1_h[CHID*CC];
__device__ __half g_wf2_h[CC*CHID];

// ============================ helpers ======================================
__device__ __forceinline__ uint32_t smem_u32(const void* p) {
    uint32_t a;
    asm("{ .reg .u64 t; cvta.to.shared.u64 t, %1; cvt.u32.u64 %0, t; }"
        : "=r"(a) : "l"(p));
    return a;
}

#define CP_ASYNC16(dst, src) \
    asm volatile("cp.async.cg.shared.global [%0], [%1], 16;" \
                 :: "r"(dst), "l"(src) : "memory")
#define CP_COMMIT()  asm volatile("cp.async.commit_group;" ::: "memory")
#define CP_WAIT0()   asm volatile("cp.async.wait_group 0;" ::: "memory")
#define CP_WAIT1()   asm volatile("cp.async.wait_group 1;" ::: "memory")

#define LDSM4(r, a) \
    asm volatile("ldmatrix.sync.aligned.m8n8.x4.shared.b16 {%0,%1,%2,%3}, [%4];" \
                 : "=r"((r)[0]), "=r"((r)[1]), "=r"((r)[2]), "=r"((r)[3]) : "r"(a))

#define MMA16816(d, a, b0, b1) \
    asm volatile("mma.sync.aligned.m16n8k16.row.col.f32.f16.f16.f32 " \
                 "{%0,%1,%2,%3}, {%4,%5,%6,%7}, {%8,%9}, {%0,%1,%2,%3};" \
                 : "+f"((d)[0]), "+f"((d)[1]), "+f"((d)[2]), "+f"((d)[3]) \
                 : "r"((a)[0]), "r"((a)[1]), "r"((a)[2]), "r"((a)[3]), \
                   "r"(b0), "r"(b1))

// ---------------------------------------------------------------------------
// Tiled weight transpose + fp16 convert: W[K,N] fp32 -> [N,K] fp16.
// ---------------------------------------------------------------------------
__global__ void wtrans_kernel(const float* __restrict__ W,
                              __half* __restrict__ O, int K, int N)
{
    __shared__ float t[32][33];
    int n0 = blockIdx.x * 32;
    int k0 = blockIdx.y * 32;
    int tx = threadIdx.x, ty = threadIdx.y;
#pragma unroll
    for (int r = ty; r < 32; r += 8)
        t[r][tx] = W[(size_t)(k0 + r) * N + n0 + tx];
    __syncthreads();
#pragma unroll
    for (int r = ty; r < 32; r += 8)
        O[(size_t)(n0 + r) * K + k0 + tx] = __float2half_rn(t[tx][r]);
}

// ---------------------------------------------------------------------------
// Fused depthwise 3x3 conv (+bias +residual) and LayerNorm.
// Block = 384 threads (channels) x 8 consecutive x-pixels.
// ---------------------------------------------------------------------------
__global__ void __launch_bounds__(384)
dwconv_ln_kernel(const float* __restrict__ x,
                 const float* __restrict__ w,
                 const float* __restrict__ cb,
                 const float* __restrict__ g,
                 const float* __restrict__ b,
                 float* __restrict__ rawOut,
                 float* __restrict__ normF,
                 __half* __restrict__ normH)
{
    int row0 = blockIdx.x * 8;
    int c    = threadIdx.x;
    int pix0 = row0 & (NT - 1);
    int y    = pix0 >> 6;
    int x0   = pix0 & 63;
    const float* xb = x + (size_t)(row0 - pix0) * CC;

    float wr[9];
#pragma unroll
    for (int t = 0; t < 9; t++) wr[t] = w[c * 9 + t];

    float col[3][10];
#pragma unroll
    for (int dy = 0; dy < 3; dy++) {
        int yy = y + dy - 1;
        bool yok = (yy >= 0 && yy < HH);
#pragma unroll
        for (int j = 0; j < 10; j++) {
            int xc = x0 + j - 1;
            col[dy][j] = (yok && xc >= 0 && xc < WW)
                ? xb[(size_t)(yy * WW + xc) * CC + c] : 0.f;
        }
    }

    float bias = cb[c];
    float v[8];
#pragma unroll
    for (int p = 0; p < 8; p++) {
        float a = bias;
#pragma unroll
        for (int dy = 0; dy < 3; dy++)
#pragma unroll
            for (int dx = 0; dx < 3; dx++)
                a += wr[dy * 3 + dx] * col[dy][p + dx];
        v[p] = col[1][p + 1] + a;
        if (rawOut) rawOut[(size_t)(row0 + p) * CC + c] = v[p];
    }

    __shared__ float redA[12][8], redB[12][8], mus[8], rsd[8];
    float s1[8], s2[8];
#pragma unroll
    for (int p = 0; p < 8; p++) { s1[p] = v[p]; s2[p] = v[p] * v[p]; }
#pragma unroll
    for (int o = 16; o > 0; o >>= 1)
#pragma unroll
        for (int p = 0; p < 8; p++) {
            s1[p] += __shfl_xor_sync(0xffffffffu, s1[p], o);
            s2[p] += __shfl_xor_sync(0xffffffffu, s2[p], o);
        }
    int wid = c >> 5, lane = c & 31;
    if (lane == 0) {
#pragma unroll
        for (int p = 0; p < 8; p++) { redA[wid][p] = s1[p]; redB[wid][p] = s2[p]; }
    }
    __syncthreads();
    if (wid < 8) {
        float a1 = (lane < 12) ? redA[lane][wid] : 0.f;
        float a2 = (lane < 12) ? redB[lane][wid] : 0.f;
#pragma unroll
        for (int o = 8; o > 0; o >>= 1) {
            a1 += __shfl_xor_sync(0xffffffffu, a1, o);
            a2 += __shfl_xor_sync(0xffffffffu, a2, o);
        }
        if (lane == 0) {
            float mu = a1 * (1.f / CC);
            mus[wid] = mu;
            rsd[wid] = rsqrtf(a2 * (1.f / CC) - mu * mu + 1e-5f);
        }
    }
    __syncthreads();
    float gg = g[c], bbv = b[c];
#pragma unroll
    for (int p = 0; p < 8; p++) {
        float o = (v[p] - mus[p]) * rsd[p] * gg + bbv;
        if (normF) normF[(size_t)(row0 + p) * CC + c] = o;
        normH[(size_t)(row0 + p) * CC + c] = __float2half_rn(o);
    }
}

// ---------------------------------------------------------------------------
// fp16 GEMM via mma.sync.  C[M,Nfull] = A @ W.
// A fp16 [M,KTOT]; B = W^T fp16 [Nfull,KTOT].
// 128x128 CTA tile, BK=64, 2-stage cp.async, 3 CTAs/SM target.
// Register-lean addressing: 2 base pointers, compile-time chunk strides.
// Smem rows: 144B stride (conflict-free ldmatrix). 8 warps 4x2; 32x64/warp.
// EPI: 0 plain fp32; 1 +bias+residual fp32; 2 +bias+GELU -> fp16.
// ---------------------------------------------------------------------------
#define TILE_B   18432              // 128 rows * 144 bytes
#define STAGE_B  (2 * TILE_B)       // A, B = 36864
#define GSMEM_BYTES (2 * STAGE_B)   // 73728

template<int KTOT, int EPI>
__global__ void __launch_bounds__(256, 3)
mma_gemm(const __half* __restrict__ Ah,
         const __half* __restrict__ Bh,
         const float* __restrict__ bias, const float* __restrict__ R,
         float* __restrict__ Cf, __half* __restrict__ Ch,
         int Nfull)
{
    extern __shared__ __align__(128) char smem[];
    const int tid  = threadIdx.x;
    const int lane = tid & 31;
    const int wid  = tid >> 5;
    const int wm   = wid & 3;
    const int wn   = wid >> 2;
    const int m0   = blockIdx.y * 128;
    const int n0   = blockIdx.x * 128;
    const uint32_t sbase = smem_u32(smem);

    // register-lean load addressing: this thread's slot = row (tid>>3),
    // 16B segment (tid&7); chunk j covers rows j*32.. so stride j*32 rows.
    const int srow = tid >> 3;
    const int sseg = tid & 7;
    const __half* gpA = Ah + (size_t)(m0 + srow) * KTOT + sseg * 8;
    const __half* gpB = Bh + (size_t)(n0 + srow) * KTOT + sseg * 8;
    const uint32_t dsoA = (uint32_t)(srow * 144 + sseg * 16);
    const uint32_t dsoB = dsoA + TILE_B;

    float acc[2][8][4];
#pragma unroll
    for (int mt = 0; mt < 2; mt++)
#pragma unroll
        for (int nt = 0; nt < 8; nt++)
#pragma unroll
            for (int q = 0; q < 4; q++) acc[mt][nt][q] = 0.f;

    constexpr int NC = KTOT / 64;
    constexpr size_t JSTRIDE = 32 * (size_t)KTOT;   // 32 rows per j-slot

    // prefetch chunk 0 -> stage 0
    {
#pragma unroll
        for (int j = 0; j < 4; j++) {
            CP_ASYNC16(sbase + dsoA + j * 4608, gpA + j * JSTRIDE);
            CP_ASYNC16(sbase + dsoB + j * 4608, gpB + j * JSTRIDE);
        }
        CP_COMMIT();
    }

    for (int c = 0; c < NC; c++) {
        const int s = c & 1;
        if (c + 1 < NC) {
            const uint32_t sb = sbase + (1 - s) * STAGE_B;
            const int ko = (c + 1) * 64;
#pragma unroll
            for (int j = 0; j < 4; j++) {
                CP_ASYNC16(sb + dsoA + j * 4608, gpA + j * JSTRIDE + ko);
                CP_ASYNC16(sb + dsoB + j * 4608, gpB + j * JSTRIDE + ko);
            }
            CP_COMMIT();
            CP_WAIT1();
        } else {
            CP_WAIT0();
        }
        __syncthreads();

        const uint32_t pa = sbase + s * STAGE_B;
#pragma unroll
        for (int ks = 0; ks < 4; ks++) {
            uint32_t af[2][4];
            const int arow = wm * 32 + (lane & 15);
            const int acol = ks * 16 + ((lane & 16) >> 1);
#pragma unroll
            for (int mt = 0; mt < 2; mt++) {
                uint32_t off = (uint32_t)((arow + mt * 16) * 144 + acol * 2);
                LDSM4(af[mt], pa + off);
            }
            const int brow = wn * 64 + ((lane & 16) >> 1) + (lane & 7);
            const int bcol = ks * 16 + (lane & 8);
#pragma unroll
            for (int p = 0; p < 4; p++) {
                uint32_t off = (uint32_t)((brow + p * 16) * 144 + bcol * 2);
                uint32_t t[4];
                LDSM4(t, pa + TILE_B + off);
                MMA16816(acc[0][2*p],   af[0], t[0], t[1]);
                MMA16816(acc[0][2*p+1], af[0], t[2], t[3]);
                MMA16816(acc[1][2*p],   af[1], t[0], t[1]);
                MMA16816(acc[1][2*p+1], af[1], t[2], t[3]);
            }
        }
        __syncthreads();
    }

    const int g  = lane >> 2;
    const int tg = (lane & 3) * 2;
#pragma unroll
    for (int mt = 0; mt < 2; mt++) {
#pragma unroll
        for (int nt = 0; nt < 8; nt++) {
            int colg = n0 + wn * 64 + nt * 8 + tg;
#pragma unroll
            for (int half_i = 0; half_i < 2; half_i++) {
                int rowg = m0 + wm * 32 + mt * 16 + g + half_i * 8;
                float v0 = acc[mt][nt][half_i * 2 + 0];
                float v1 = acc[mt][nt][half_i * 2 + 1];
                size_t off = (size_t)rowg * Nfull + colg;
                if (EPI == 0) {
                    float2 o = {v0, v1};
                    *(float2*)(Cf + off) = o;
                } else if (EPI == 1) {
                    v0 += bias[colg]     + R[off];
                    v1 += bias[colg + 1] + R[off + 1];
                    float2 o = {v0, v1};
                    *(float2*)(Cf + off) = o;
                } else {
                    v0 += bias[colg];
                    v1 += bias[colg + 1];
                    v0 = 0.5f * v0 * (1.f + erff(v0 * 0.70710678118654752f));
                    v1 = 0.5f * v1 * (1.f + erff(v1 * 0.70710678118654752f));
                    __half2 hp;
                    hp.x = __float2half_rn(v0);
                    hp.y = __float2half_rn(v1);
                    *(__half2*)(Ch + off) = hp;
                }
            }
        }
    }
}

// ---------------------------------------------------------------------------
// channel attention
// ---------------------------------------------------------------------------
__global__ void zero_kernel(float* __restrict__ p, int n)
{
    int i = blockIdx.x * blockDim.x + threadIdx.x;
    if (i < n) p[i] = 0.f;
}

__global__ void attn_logits_kernel(const float* __restrict__ kv,
                                   float* __restrict__ logits)
{
    int bh = blockIdx.x;
    int b = bh >> 3, head = bh & 7;
    int nstart = blockIdx.y * 512;

    __shared__ float4 ks4[64][12];
    __shared__ float4 vs4[64][12];

    int tid = threadIdx.x;               // 0..143
    int d4 = tid % 12;
    int e4 = tid / 12;
    float acc[4][4] = {{0.f,0.f,0.f,0.f},{0.f,0.f,0.f,0.f},
                       {0.f,0.f,0.f,0.f},{0.f,0.f,0.f,0.f}};

    const float* base = kv + (size_t)b * NT * (2 * CC) + head * DH;

    for (int nn = 0; nn < 512; nn += 64) {
        __syncthreads();
        for (int idx = tid; idx < 64 * 12; idx += 144) {
            int r = idx / 12, q = idx % 12;
            const float* rp = base + (size_t)(nstart + nn + r) * (2 * CC);
            ks4[r][q] = *(const float4*)(rp + q * 4);
            vs4[r][q] = *(const float4*)(rp + CC + q * 4);
        }
        __syncthreads();
#pragma unroll 4
        for (int r = 0; r < 64; r++) {
            float4 kk = ks4[r][d4];
            float4 vv = vs4[r][e4];
            acc[0][0] += kk.x*vv.x; acc[0][1] += kk.x*vv.y;
            acc[0][2] += kk.x*vv.z; acc[0][3] += kk.x*vv.w;
            acc[1][0] += kk.y*vv.x; acc[1][1] += kk.y*vv.y;
            acc[1][2] += kk.y*vv.z; acc[1][3] += kk.y*vv.w;
            acc[2][0] += kk.z*vv.x; acc[2][1] += kk.z*vv.y;
            acc[2][2] += kk.z*vv.z; acc[2][3] += kk.z*vv.w;
            acc[3][0] += kk.w*vv.x; acc[3][1] += kk.w*vv.y;
            acc[3][2] += kk.w*vv.z; acc[3][3] += kk.w*vv.w;
        }
    }
    int d0 = d4 * 4, e0 = e4 * 4;
#pragma unroll
    for (int i = 0; i < 4; i++)
#pragma unroll
        for (int j = 0; j < 4; j++)
            atomicAdd(&logits[((size_t)bh * DH + d0 + i) * DH + e0 + j], acc[i][j]);
}

__global__ void attn_softmax_kernel(float* __restrict__ logits)
{
    int gwarp = (int)((blockIdx.x * blockDim.x + threadIdx.x) >> 5);
    int lane = threadIdx.x & 31;
    if (gwarp >= BB * NHEAD * DH) return;
    float* L = logits + (size_t)gwarp * DH;
    const float scale = 0.14433756729740643f;   // 48^-0.5

    float a  = L[lane] * scale;
    float b2 = (lane < 16) ? L[32 + lane] * scale : -INFINITY;
    float m = fmaxf(a, b2);
#pragma unroll
    for (int o = 16; o > 0; o >>= 1) m = fmaxf(m, __shfl_xor_sync(0xffffffffu, m, o));
    float ea = expf(a - m);
    float eb = (lane < 16) ? expf(b2 - m) : 0.f;
    float s = ea + eb;
#pragma unroll
    for (int o = 16; o > 0; o >>= 1) s += __shfl_xor_sync(0xffffffffu, s, o);
    float inv = 1.f / s;
    L[lane] = ea * inv;
    if (lane < 16) L[32 + lane] = eb * inv;
}

__global__ void attn_apply_kernel(const float* __restrict__ q,
                                  const float* __restrict__ attn,
                                  __half* __restrict__ aoh)
{
    int row0 = blockIdx.x * 8;
    int c = threadIdx.x;                 // 0..383
    __shared__ float qs[8][CC];
#pragma unroll
    for (int r = 0; r < 8; r++) qs[r][c] = q[(size_t)(row0 + r) * CC + c];
    __syncthreads();

    int head = c / DH, dd = c - head * DH;
    int b = row0 >> 12;
    const float* arow = attn + ((size_t)((b * NHEAD + head) * DH + dd)) * DH;

    float acc[8] = {0.f,0.f,0.f,0.f,0.f,0.f,0.f,0.f};
#pragma unroll
    for (int e = 0; e < DH; e++) {
        float a = arow[e];
#pragma unroll
        for (int r = 0; r < 8; r++) acc[r] += a * qs[r][head * DH + e];
    }
#pragma unroll
    for (int r = 0; r < 8; r++)
        aoh[(size_t)(row0 + r) * CC + c] = __float2half_rn(acc[r]);
}

// ---------------------------------------------------------------------------
extern "C" void kernel_launch(void* const* d_in, const int* in_sizes, int n_in,
                              void* d_out, int out_size)
{
    const float* x      = (const float*)d_in[0];
    const float* src    = (const float*)d_in[1];
    const float* cpe0_w = (const float*)d_in[4];
    const float* cpe0_b = (const float*)d_in[5];
    const float* cpe1_w = (const float*)d_in[6];
    const float* cpe1_b = (const float*)d_in[7];
    const float* n1g    = (const float*)d_in[8];
    const float* n1b    = (const float*)d_in[9];
    const float* q_w    = (const float*)d_in[10];
    const float* kv_w   = (const float*)d_in[11];
    const float* pj_w   = (const float*)d_in[12];
    const float* pj_b   = (const float*)d_in[13];
    const float* n2g    = (const float*)d_in[14];
    const float* n2b    = (const float*)d_in[15];
    const float* f1w    = (const float*)d_in[16];
    const float* f1b    = (const float*)d_in[17];
    const float* f2w    = (const float*)d_in[18];
    const float* f2b    = (const float*)d_in[19];
    float* out = (float*)d_out;

    float *p_xn, *p_q, *p_kv, *p_attn, *p_x2, *p_x3;
    cudaGetSymbolAddress((void**)&p_xn,  g_xn);
    cudaGetSymbolAddress((void**)&p_q,   g_q);
    cudaGetSymbolAddress((void**)&p_kv,  g_kv);
    cudaGetSymbolAddress((void**)&p_attn,g_attn);
    cudaGetSymbolAddress((void**)&p_x2,  g_x2);
    cudaGetSymbolAddress((void**)&p_x3,  g_x3);

    __half *xnh,*snh,*aoh,*h0h,*h1h;
    __half *wqh,*wkvh,*wpjh,*wf1h,*wf2h;
    cudaGetSymbolAddress((void**)&xnh, g_xn_h);
    cudaGetSymbolAddress((void**)&snh, g_sn_h);
    cudaGetSymbolAddress((void**)&aoh, g_ao_h);
    cudaGetSymbolAddress((void**)&h0h, g_h0_h);
    cudaGetSymbolAddress((void**)&h1h, g_h1_h);
    cudaGetSymbolAddress((void**)&wqh, g_wq_h);
    cudaGetSymbolAddress((void**)&wkvh,g_wkv_h);
    cudaGetSymbolAddress((void**)&wpjh,g_wpj_h);
    cudaGetSymbolAddress((void**)&wf1h,g_wf1_h);
    cudaGetSymbolAddress((void**)&wf2h,g_wf2_h);

    cudaFuncSetAttribute(mma_gemm<384, 0>,  cudaFuncAttributeMaxDynamicSharedMemorySize, GSMEM_BYTES);
    cudaFuncSetAttribute(mma_gemm<384, 1>,  cudaFuncAttributeMaxDynamicSharedMemorySize, GSMEM_BYTES);
    cudaFuncSetAttribute(mma_gemm<384, 2>,  cudaFuncAttributeMaxDynamicSharedMemorySize, GSMEM_BYTES);
    cudaFuncSetAttribute(mma_gemm<1536, 1>, cudaFuncAttributeMaxDynamicSharedMemorySize, GSMEM_BYTES);

    dim3 tb(32, 8);

    // 0: q weight transpose; 1: fused CPE0+LN on x; 2: kv weight transpose
    wtrans_kernel<<<dim3(CC/32, CC/32), tb>>>(q_w, wqh, CC, CC);
    dwconv_ln_kernel<<<MROWS/8, CC>>>(x, cpe0_w, cpe0_b, n1g, n1b,
                                      nullptr, p_xn, xnh);
    wtrans_kernel<<<dim3(2*CC/32, CC/32), tb>>>(kv_w, wkvh, CC, 2*CC);

    // 3: q projection (ncu profiling slot targets this launch)
    mma_gemm<384, 0><<<dim3(CC/128, MROWS/128), 256, GSMEM_BYTES>>>(
        xnh, wqh, nullptr, nullptr, p_q, nullptr, CC);

    // 4: fused CPE0+LN on source; 5: kv projection
    dwconv_ln_kernel<<<MROWS/8, CC>>>(src, cpe0_w, cpe0_b, n1g, n1b,
                                      nullptr, nullptr, snh);
    mma_gemm<384, 0><<<dim3(2*CC/128, MROWS/128), 256, GSMEM_BYTES>>>(
        snh, wkvh, nullptr, nullptr, p_kv, nullptr, 2*CC);

    // 6-9: channel attention
    zero_kernel<<<(BB*NHEAD*DH*DH + 255)/256, 256>>>(p_attn, BB*NHEAD*DH*DH);
    attn_logits_kernel<<<dim3(BB*NHEAD, 8), 144>>>(p_kv, p_attn);
    attn_softmax_kernel<<<(BB*NHEAD*DH + 7)/8, 256>>>(p_attn);
    attn_apply_kernel<<<MROWS/8, CC>>>(p_q, p_attn, aoh);

    // 10-11: proj + bias + residual(xn)
    wtrans_kernel<<<dim3(CC/32, CC/32), tb>>>(pj_w, wpjh, CC, CC);
    mma_gemm<384, 1><<<dim3(CC/128, MROWS/128), 256, GSMEM_BYTES>>>(
        aoh, wpjh, pj_b, p_xn, p_x2, nullptr, CC);

    // 12: fused CPE1+LN (x3 fp32 conv result kept as fc2 residual)
    dwconv_ln_kernel<<<MROWS/8, CC>>>(p_x2, cpe1_w, cpe1_b, n2g, n2b,
                                      p_x3, nullptr, h0h);

    // 13-16: MLP
    wtrans_kernel<<<dim3(CHID/32, CC/32), tb>>>(f1w, wf1h, CC, CHID);
    wtrans_kernel<<<dim3(CC/32, CHID/32), tb>>>(f2w, wf2h, CHID, CC);
    mma_gemm<384, 2><<<dim3(CHID/128, MROWS/128), 256, GSMEM_BYTES>>>(
        h0h, wf1h, f1b, nullptr, nullptr, h1h, CHID);
    mma_gemm<1536, 1><<<dim3(CC/128, MROWS/128), 256, GSMEM_BYTES>>>(
        h1h, wf2h, f2b, p_x3, out, nullptr, CC);
}

// round 13
// speedup vs baseline: 1.2478x; 1.2478x over previous
#include <cuda_runtime.h>
#include <cuda_fp16.h>
#include <math.h>
#include <cstdint>

// ---------------------------------------------------------------------------
// ChannelBlock on GB300 (compute_103 base target):
// fp16 mma.sync GEMMs (R8-proven core) + register-lean sliding-window
// fused dwconv+LayerNorm.  (R11 resubmit — R12 bench was an infra failure.)
// Shapes: B=8, H=W=64, N=4096, C=384, heads=8, d=48, Ch=1536, M=B*N=32768
// ---------------------------------------------------------------------------

#define BB     8
#define HH     64
#define WW     64
#define NT     4096
#define CC     384
#define NHEAD  8
#define DH     48
#define MROWS  (BB*NT)     // 32768
#define CHID   1536

// ---- scratch (static device arrays; no allocation allowed) ----------------
__device__ float g_xn [MROWS*CC];
__device__ float g_q  [MROWS*CC];
__device__ float g_kv [MROWS*2*CC];
__device__ float g_attn[BB*NHEAD*DH*DH];
__device__ float g_x2 [MROWS*CC];
__device__ float g_x3 [MROWS*CC];

__device__ __half g_xn_h[MROWS*CC];
__device__ __half g_sn_h[MROWS*CC];
__device__ __half g_ao_h[MROWS*CC];
__device__ __half g_h0_h[MROWS*CC];
__device__ __half g_h1_h[MROWS*CHID];

// weights, fp16, TRANSPOSED [N,K] layout (GEMM B operand)
__device__ __half g_wq_h [CC*CC];
__device__ __half g_wkv_h[2*CC*CC];
__device__ __half g_wpj_h[CC*CC];
__device__ __half g_wf1_h[CHID*CC];
__device__ __half g_wf2_h[CC*CHID];

// ============================ helpers ======================================
__device__ __forceinline__ uint32_t smem_u32(const void* p) {
    uint32_t a;
    asm("{ .reg .u64 t; cvta.to.shared.u64 t, %1; cvt.u32.u64 %0, t; }"
        : "=r"(a) : "l"(p));
    return a;
}

#define CP_ASYNC16(dst, src) \
    asm volatile("cp.async.cg.shared.global [%0], [%1], 16;" \
                 :: "r"(dst), "l"(src) : "memory")
#define CP_COMMIT()  asm volatile("cp.async.commit_group;" ::: "memory")
#define CP_WAIT0()   asm volatile("cp.async.wait_group 0;" ::: "memory")
#define CP_WAIT1()   asm volatile("cp.async.wait_group 1;" ::: "memory")

#define LDSM4(r, a) \
    asm volatile("ldmatrix.sync.aligned.m8n8.x4.shared.b16 {%0,%1,%2,%3}, [%4];" \
                 : "=r"((r)[0]), "=r"((r)[1]), "=r"((r)[2]), "=r"((r)[3]) : "r"(a))

#define MMA16816(d, a, b) \
    asm volatile("mma.sync.aligned.m16n8k16.row.col.f32.f16.f16.f32 " \
                 "{%0,%1,%2,%3}, {%4,%5,%6,%7}, {%8,%9}, {%0,%1,%2,%3};" \
                 : "+f"((d)[0]), "+f"((d)[1]), "+f"((d)[2]), "+f"((d)[3]) \
                 : "r"((a)[0]), "r"((a)[1]), "r"((a)[2]), "r"((a)[3]), \
                   "r"((b)[0]), "r"((b)[1]))

// ---------------------------------------------------------------------------
// Tiled weight transpose + fp16 convert: W[K,N] fp32 -> [N,K] fp16.
// ---------------------------------------------------------------------------
__global__ void wtrans_kernel(const float* __restrict__ W,
                              __half* __restrict__ O, int K, int N)
{
    __shared__ float t[32][33];
    int n0 = blockIdx.x * 32;
    int k0 = blockIdx.y * 32;
    int tx = threadIdx.x, ty = threadIdx.y;
#pragma unroll
    for (int r = ty; r < 32; r += 8)
        t[r][tx] = W[(size_t)(k0 + r) * N + n0 + tx];
    __syncthreads();
#pragma unroll
    for (int r = ty; r < 32; r += 8)
        O[(size_t)(n0 + r) * K + k0 + tx] = __float2half_rn(t[tx][r]);
}

// ---------------------------------------------------------------------------
// Fused depthwise 3x3 conv (+bias +residual) and LayerNorm.
// Block = 384 threads (channels) x 8 consecutive x-pixels (same y).
// Sliding 3x3 column window in 9 registers (rotated), not col[3][10]:
// minimizes live registers to avoid spills.
// ---------------------------------------------------------------------------
__global__ void __launch_bounds__(384)
dwconv_ln_kernel(const float* __restrict__ x,
                 const float* __restrict__ w,
                 const float* __restrict__ cb,
                 const float* __restrict__ g,
                 const float* __restrict__ b,
                 float* __restrict__ rawOut,
                 float* __restrict__ normF,
                 __half* __restrict__ normH)
{
    int row0 = blockIdx.x * 8;
    int c    = threadIdx.x;
    int pix0 = row0 & (NT - 1);
    int y    = pix0 >> 6;
    int x0   = pix0 & 63;
    const float* xb = x + (size_t)(row0 - pix0) * CC + c;

    float wr[9];
#pragma unroll
    for (int t = 0; t < 9; t++) wr[t] = w[c * 9 + t];

    const bool y0ok = (y > 0);
    const bool y2ok = (y < HH - 1);

    float c0[3], c1[3], c2[3];

#define LOADC(xc, col) do {                                                   \
    int _xc = (xc);                                                           \
    bool _xok = (_xc >= 0) && (_xc < WW);                                     \
    (col)[0] = (_xok && y0ok) ? xb[(size_t)((y - 1) * WW + _xc) * CC] : 0.f;  \
    (col)[1] = (_xok)         ? xb[(size_t)( y      * WW + _xc) * CC] : 0.f;  \
    (col)[2] = (_xok && y2ok) ? xb[(size_t)((y + 1) * WW + _xc) * CC] : 0.f;  \
} while (0)

    LOADC(x0 - 1, c0);
    LOADC(x0,     c1);

    float bias = cb[c];
    float v[8];
#pragma unroll
    for (int p = 0; p < 8; p++) {
        LOADC(x0 + p + 1, c2);
        float a = bias
            + wr[0] * c0[0] + wr[1] * c1[0] + wr[2] * c2[0]
            + wr[3] * c0[1] + wr[4] * c1[1] + wr[5] * c2[1]
            + wr[6] * c0[2] + wr[7] * c1[2] + wr[8] * c2[2];
        v[p] = c1[1] + a;          // residual = center pixel value
        if (rawOut) rawOut[(size_t)(row0 + p) * CC + c] = v[p];
        c0[0] = c1[0]; c0[1] = c1[1]; c0[2] = c1[2];
        c1[0] = c2[0]; c1[1] = c2[1]; c1[2] = c2[2];
    }
#undef LOADC

    // batched LayerNorm over C=384 for 8 pixels; sequential per-pixel shuffle
    // reductions (2 live temps, not 16).
    __shared__ float redA[12][8], redB[12][8], mus[8], rsd[8];
    int wid = c >> 5, lane = c & 31;
#pragma unroll
    for (int p = 0; p < 8; p++) {
        float s1 = v[p], s2 = v[p] * v[p];
#pragma unroll
        for (int o = 16; o > 0; o >>= 1) {
            s1 += __shfl_xor_sync(0xffffffffu, s1, o);
            s2 += __shfl_xor_sync(0xffffffffu, s2, o);
        }
        if (lane == 0) { redA[wid][p] = s1; redB[wid][p] = s2; }
    }
    __syncthreads();
    if (wid < 8) {                 // warp p reduces pixel p (12 partials)
        float a1 = (lane < 12) ? redA[lane][wid] : 0.f;
        float a2 = (lane < 12) ? redB[lane][wid] : 0.f;
#pragma unroll
        for (int o = 8; o > 0; o >>= 1) {
            a1 += __shfl_xor_sync(0xffffffffu, a1, o);
            a2 += __shfl_xor_sync(0xffffffffu, a2, o);
        }
        if (lane == 0) {
            float mu = a1 * (1.f / CC);
            mus[wid] = mu;
            rsd[wid] = rsqrtf(a2 * (1.f / CC) - mu * mu + 1e-5f);
        }
    }
    __syncthreads();
    float gg = g[c], bbv = b[c];
#pragma unroll
    for (int p = 0; p < 8; p++) {
        float o = (v[p] - mus[p]) * rsd[p] * gg + bbv;
        if (normF) normF[(size_t)(row0 + p) * CC + c] = o;
        normH[(size_t)(row0 + p) * CC + c] = __float2half_rn(o);
    }
}

// ---------------------------------------------------------------------------
// fp16 GEMM via mma.sync (R8-proven core, verbatim).  C[M,Nfull] = A @ W.
// A fp16 [M,KTOT]; B = W^T fp16 [Nfull,KTOT].
// 128x128 CTA tile, BK=64, double-buffered cp.async.
// Smem rows: 144B stride (conflict-free ldmatrix). 8 warps 4x2; 32x64/warp.
// EPI: 0 plain fp32; 1 +bias+residual fp32; 2 +bias+GELU -> fp16.
// ---------------------------------------------------------------------------
#define TILE_B   18432              // 128 rows * 144 bytes
#define STAGE_B  (2 * TILE_B)       // A, B = 36864
#define GSMEM_BYTES (2 * STAGE_B)   // 73728

template<int KTOT, int EPI>
__global__ void __launch_bounds__(256)
mma_gemm(const __half* __restrict__ Ah,
         const __half* __restrict__ Bh,
         const float* __restrict__ bias, const float* __restrict__ R,
         float* __restrict__ Cf, __half* __restrict__ Ch,
         int Nfull)
{
    extern __shared__ __align__(128) char smem[];
    const int tid  = threadIdx.x;
    const int lane = tid & 31;
    const int wid  = tid >> 5;
    const int wm   = wid & 3;
    const int wn   = wid >> 2;
    const int m0   = blockIdx.y * 128;
    const int n0   = blockIdx.x * 128;
    const uint32_t sbase = smem_u32(smem);

    // per-thread load slots: 2048 16B chunks (A 1024 + B 1024) / 256 = 8
    const __half* gp[8];
    uint32_t dso[8];
#pragma unroll
    for (int j = 0; j < 8; j++) {
        int idx  = j * 256 + tid;
        int tile = idx >> 10;           // 0=A 1=B
        int rid  = (idx >> 3) & 127;
        int seg  = idx & 7;
        const __half* base = (tile == 0) ? Ah : Bh;
        int rowg = ((tile == 0) ? m0 : n0) + rid;
        gp[j]  = base + (size_t)rowg * KTOT + seg * 8;
        dso[j] = (uint32_t)(tile * TILE_B + rid * 144 + seg * 16);
    }

    float acc[2][8][4];
#pragma unroll
    for (int mt = 0; mt < 2; mt++)
#pragma unroll
        for (int nt = 0; nt < 8; nt++)
#pragma unroll
            for (int q = 0; q < 4; q++) acc[mt][nt][q] = 0.f;

    constexpr int NC = KTOT / 64;

    {
        uint32_t sb = sbase;
#pragma unroll
        for (int j = 0; j < 8; j++) CP_ASYNC16(sb + dso[j], gp[j]);
        CP_COMMIT();
    }

    for (int c = 0; c < NC; c++) {
        const int s = c & 1;
        if (c + 1 < NC) {
            uint32_t sb = sbase + (1 - s) * STAGE_B;
            const int ko = (c + 1) * 64;
#pragma unroll
            for (int j = 0; j < 8; j++) CP_ASYNC16(sb + dso[j], gp[j] + ko);
            CP_COMMIT();
            CP_WAIT1();
        } else {
            CP_WAIT0();
        }
        __syncthreads();

        const uint32_t pa = sbase + s * STAGE_B;
#pragma unroll
        for (int ks = 0; ks < 4; ks++) {
            uint32_t af[2][4];
            const int arow = wm * 32 + (lane & 15);
            const int acol = ks * 16 + ((lane & 16) >> 1);
#pragma unroll
            for (int mt = 0; mt < 2; mt++) {
                uint32_t off = (uint32_t)((arow + mt * 16) * 144 + acol * 2);
                LDSM4(af[mt], pa + off);
            }
            uint32_t bf[8][2];
            const int brow = wn * 64 + ((lane & 16) >> 1) + (lane & 7);
            const int bcol = ks * 16 + (lane & 8);
#pragma unroll
            for (int p = 0; p < 4; p++) {
                uint32_t off = (uint32_t)((brow + p * 16) * 144 + bcol * 2);
                uint32_t t[4];
                LDSM4(t, pa + TILE_B + off);
                bf[2*p][0]   = t[0]; bf[2*p][1]   = t[1];
                bf[2*p+1][0] = t[2]; bf[2*p+1][1] = t[3];
            }
#pragma unroll
            for (int mt = 0; mt < 2; mt++)
#pragma unroll
                for (int nt = 0; nt < 8; nt++)
                    MMA16816(acc[mt][nt], af[mt], bf[nt]);
        }
        __syncthreads();
    }

    const int g  = lane >> 2;
    const int tg = (lane & 3) * 2;
#pragma unroll
    for (int mt = 0; mt < 2; mt++) {
#pragma unroll
        for (int nt = 0; nt < 8; nt++) {
            int colg = n0 + wn * 64 + nt * 8 + tg;
#pragma unroll
            for (int half_i = 0; half_i < 2; half_i++) {
                int rowg = m0 + wm * 32 + mt * 16 + g + half_i * 8;
                float v0 = acc[mt][nt][half_i * 2 + 0];
                float v1 = acc[mt][nt][half_i * 2 + 1];
                size_t off = (size_t)rowg * Nfull + colg;
                if (EPI == 0) {
                    float2 o = {v0, v1};
                    *(float2*)(Cf + off) = o;
                } else if (EPI == 1) {
                    v0 += bias[colg]     + R[off];
                    v1 += bias[colg + 1] + R[off + 1];
                    float2 o = {v0, v1};
                    *(float2*)(Cf + off) = o;
                } else {
                    v0 += bias[colg];
                    v1 += bias[colg + 1];
                    v0 = 0.5f * v0 * (1.f + erff(v0 * 0.70710678118654752f));
                    v1 = 0.5f * v1 * (1.f + erff(v1 * 0.70710678118654752f));
                    __half2 hp;
                    hp.x = __float2half_rn(v0);
                    hp.y = __float2half_rn(v1);
                    *(__half2*)(Ch + off) = hp;
                }
            }
        }
    }
}

// ---------------------------------------------------------------------------
// channel attention
// ---------------------------------------------------------------------------
__global__ void zero_kernel(float* __restrict__ p, int n)
{
    int i = blockIdx.x * blockDim.x + threadIdx.x;
    if (i < n) p[i] = 0.f;
}

__global__ void attn_logits_kernel(const float* __restrict__ kv,
                                   float* __restrict__ logits)
{
    int bh = blockIdx.x;
    int b = bh >> 3, head = bh & 7;
    int nstart = blockIdx.y * 512;

    __shared__ float4 ks4[64][12];
    __shared__ float4 vs4[64][12];

    int tid = threadIdx.x;               // 0..143
    int d4 = tid % 12;
    int e4 = tid / 12;
    float acc[4][4] = {{0.f,0.f,0.f,0.f},{0.f,0.f,0.f,0.f},
                       {0.f,0.f,0.f,0.f},{0.f,0.f,0.f,0.f}};

    const float* base = kv + (size_t)b * NT * (2 * CC) + head * DH;

    for (int nn = 0; nn < 512; nn += 64) {
        __syncthreads();
        for (int idx = tid; idx < 64 * 12; idx += 144) {
            int r = idx / 12, q = idx % 12;
            const float* rp = base + (size_t)(nstart + nn + r) * (2 * CC);
            ks4[r][q] = *(const float4*)(rp + q * 4);
            vs4[r][q] = *(const float4*)(rp + CC + q * 4);
        }
        __syncthreads();
#pragma unroll 4
        for (int r = 0; r < 64; r++) {
            float4 kk = ks4[r][d4];
            float4 vv = vs4[r][e4];
            acc[0][0] += kk.x*vv.x; acc[0][1] += kk.x*vv.y;
            acc[0][2] += kk.x*vv.z; acc[0][3] += kk.x*vv.w;
            acc[1][0] += kk.y*vv.x; acc[1][1] += kk.y*vv.y;
            acc[1][2] += kk.y*vv.z; acc[1][3] += kk.y*vv.w;
            acc[2][0] += kk.z*vv.x; acc[2][1] += kk.z*vv.y;
            acc[2][2] += kk.z*vv.z; acc[2][3] += kk.z*vv.w;
            acc[3][0] += kk.w*vv.x; acc[3][1] += kk.w*vv.y;
            acc[3][2] += kk.w*vv.z; acc[3][3] += kk.w*vv.w;
        }
    }
    int d0 = d4 * 4, e0 = e4 * 4;
#pragma unroll
    for (int i = 0; i < 4; i++)
#pragma unroll
        for (int j = 0; j < 4; j++)
            atomicAdd(&logits[((size_t)bh * DH + d0 + i) * DH + e0 + j], acc[i][j]);
}

__global__ void attn_softmax_kernel(float* __restrict__ logits)
{
    int gwarp = (int)((blockIdx.x * blockDim.x + threadIdx.x) >> 5);
    int lane = threadIdx.x & 31;
    if (gwarp >= BB * NHEAD * DH) return;
    float* L = logits + (size_t)gwarp * DH;
    const float scale = 0.14433756729740643f;   // 48^-0.5

    float a  = L[lane] * scale;
    float b2 = (lane < 16) ? L[32 + lane] * scale : -INFINITY;
    float m = fmaxf(a, b2);
#pragma unroll
    for (int o = 16; o > 0; o >>= 1) m = fmaxf(m, __shfl_xor_sync(0xffffffffu, m, o));
    float ea = expf(a - m);
    float eb = (lane < 16) ? expf(b2 - m) : 0.f;
    float s = ea + eb;
#pragma unroll
    for (int o = 16; o > 0; o >>= 1) s += __shfl_xor_sync(0xffffffffu, s, o);
    float inv = 1.f / s;
    L[lane] = ea * inv;
    if (lane < 16) L[32 + lane] = eb * inv;
}

__global__ void attn_apply_kernel(const float* __restrict__ q,
                                  const float* __restrict__ attn,
                                  __half* __restrict__ aoh)
{
    int row0 = blockIdx.x * 8;
    int c = threadIdx.x;                 // 0..383
    __shared__ float qs[8][CC];
#pragma unroll
    for (int r = 0; r < 8; r++) qs[r][c] = q[(size_t)(row0 + r) * CC + c];
    __syncthreads();

    int head = c / DH, dd = c - head * DH;
    int b = row0 >> 12;
    const float* arow = attn + ((size_t)((b * NHEAD + head) * DH + dd)) * DH;

    float acc[8] = {0.f,0.f,0.f,0.f,0.f,0.f,0.f,0.f};
#pragma unroll
    for (int e = 0; e < DH; e++) {
        float a = arow[e];
#pragma unroll
        for (int r = 0; r < 8; r++) acc[r] += a * qs[r][head * DH + e];
    }
#pragma unroll
    for (int r = 0; r < 8; r++)
        aoh[(size_t)(row0 + r) * CC + c] = __float2half_rn(acc[r]);
}

// ---------------------------------------------------------------------------
extern "C" void kernel_launch(void* const* d_in, const int* in_sizes, int n_in,
                              void* d_out, int out_size)
{
    const float* x      = (const float*)d_in[0];
    const float* src    = (const float*)d_in[1];
    const float* cpe0_w = (const float*)d_in[4];
    const float* cpe0_b = (const float*)d_in[5];
    const float* cpe1_w = (const float*)d_in[6];
    const float* cpe1_b = (const float*)d_in[7];
    const float* n1g    = (const float*)d_in[8];
    const float* n1b    = (const float*)d_in[9];
    const float* q_w    = (const float*)d_in[10];
    const float* kv_w   = (const float*)d_in[11];
    const float* pj_w   = (const float*)d_in[12];
    const float* pj_b   = (const float*)d_in[13];
    const float* n2g    = (const float*)d_in[14];
    const float* n2b    = (const float*)d_in[15];
    const float* f1w    = (const float*)d_in[16];
    const float* f1b    = (const float*)d_in[17];
    const float* f2w    = (const float*)d_in[18];
    const float* f2b    = (const float*)d_in[19];
    float* out = (float*)d_out;

    float *p_xn, *p_q, *p_kv, *p_attn, *p_x2, *p_x3;
    cudaGetSymbolAddress((void**)&p_xn,  g_xn);
    cudaGetSymbolAddress((void**)&p_q,   g_q);
    cudaGetSymbolAddress((void**)&p_kv,  g_kv);
    cudaGetSymbolAddress((void**)&p_attn,g_attn);
    cudaGetSymbolAddress((void**)&p_x2,  g_x2);
    cudaGetSymbolAddress((void**)&p_x3,  g_x3);

    __half *xnh,*snh,*aoh,*h0h,*h1h;
    __half *wqh,*wkvh,*wpjh,*wf1h,*wf2h;
    cudaGetSymbolAddress((void**)&xnh, g_xn_h);
    cudaGetSymbolAddress((void**)&snh, g_sn_h);
    cudaGetSymbolAddress((void**)&aoh, g_ao_h);
    cudaGetSymbolAddress((void**)&h0h, g_h0_h);
    cudaGetSymbolAddress((void**)&h1h, g_h1_h);
    cudaGetSymbolAddress((void**)&wqh, g_wq_h);
    cudaGetSymbolAddress((void**)&wkvh,g_wkv_h);
    cudaGetSymbolAddress((void**)&wpjh,g_wpj_h);
    cudaGetSymbolAddress((void**)&wf1h,g_wf1_h);
    cudaGetSymbolAddress((void**)&wf2h,g_wf2_h);

    cudaFuncSetAttribute(mma_gemm<384, 0>,  cudaFuncAttributeMaxDynamicSharedMemorySize, GSMEM_BYTES);
    cudaFuncSetAttribute(mma_gemm<384, 1>,  cudaFuncAttributeMaxDynamicSharedMemorySize, GSMEM_BYTES);
    cudaFuncSetAttribute(mma_gemm<384, 2>,  cudaFuncAttributeMaxDynamicSharedMemorySize, GSMEM_BYTES);
    cudaFuncSetAttribute(mma_gemm<1536, 1>, cudaFuncAttributeMaxDynamicSharedMemorySize, GSMEM_BYTES);

    dim3 tb(32, 8);

    // Launch order: index 5 (ncu -s 5 -c 1 slot) = dwconv_ln on src.
    // 0-2: weight transposes (q, kv, pj)
    wtrans_kernel<<<dim3(CC/32, CC/32), tb>>>(q_w, wqh, CC, CC);
    wtrans_kernel<<<dim3(2*CC/32, CC/32), tb>>>(kv_w, wkvh, CC, 2*CC);
    wtrans_kernel<<<dim3(CC/32, CC/32), tb>>>(pj_w, wpjh, CC, CC);

    // 3: fused CPE0+LN on x;  4: q projection;  5: fused CPE0+LN on src
    dwconv_ln_kernel<<<MROWS/8, CC>>>(x, cpe0_w, cpe0_b, n1g, n1b,
                                      nullptr, p_xn, xnh);
    mma_gemm<384, 0><<<dim3(CC/128, MROWS/128), 256, GSMEM_BYTES>>>(
        xnh, wqh, nullptr, nullptr, p_q, nullptr, CC);
    dwconv_ln_kernel<<<MROWS/8, CC>>>(src, cpe0_w, cpe0_b, n1g, n1b,
                                      nullptr, nullptr, snh);

    // 6: kv projection
    mma_gemm<384, 0><<<dim3(2*CC/128, MROWS/128), 256, GSMEM_BYTES>>>(
        snh, wkvh, nullptr, nullptr, p_kv, nullptr, 2*CC);

    // 7-10: channel attention
    zero_kernel<<<(BB*NHEAD*DH*DH + 255)/256, 256>>>(p_attn, BB*NHEAD*DH*DH);
    attn_logits_kernel<<<dim3(BB*NHEAD, 8), 144>>>(p_kv, p_attn);
    attn_softmax_kernel<<<(BB*NHEAD*DH + 7)/8, 256>>>(p_attn);
    attn_apply_kernel<<<MROWS/8, CC>>>(p_q, p_attn, aoh);

    // 11: proj + bias + residual(xn)
    mma_gemm<384, 1><<<dim3(CC/128, MROWS/128), 256, GSMEM_BYTES>>>(
        aoh, wpjh, pj_b, p_xn, p_x2, nullptr, CC);

    // 12: fused CPE1+LN (x3 fp32 conv result kept as fc2 residual)
    dwconv_ln_kernel<<<MROWS/8, CC>>>(p_x2, cpe1_w, cpe1_b, n2g, n2b,
                                      p_x3, nullptr, h0h);

    // 13-16: MLP
    wtrans_kernel<<<dim3(CHID/32, CC/32), tb>>>(f1w, wf1h, CC, CHID);
    wtrans_kernel<<<dim3(CC/32, CHID/32), tb>>>(f2w, wf2h, CHID, CC);
    mma_gemm<384, 2><<<dim3(CHID/128, MROWS/128), 256, GSMEM_BYTES>>>(
        h0h, wf1h, f1b, nullptr, nullptr, h1h, CHID);
    mma_gemm<1536, 1><<<dim3(CC/128, MROWS/128), 256, GSMEM_BYTES>>>(
        h1h, wf2h, f2b, p_x3, out, nullptr, CC);
}

// round 16
// speedup vs baseline: 1.2778x; 1.0241x over previous
#include <cuda_runtime.h>
#include <cuda_fp16.h>
#include <math.h>
#include <cstdint>

// ---------------------------------------------------------------------------
// ChannelBlock on GB300 (compute_103 base target):
// fp16 mma.sync GEMMs (R8-proven core) + sliding-window dwconv with
// smem-transposed LayerNorm reduction (8 reducing warps).
// Shapes: B=8, H=W=64, N=4096, C=384, heads=8, d=48, Ch=1536, M=B*N=32768
// ---------------------------------------------------------------------------

#define BB     8
#define HH     64
#define WW     64
#define NT     4096
#define CC     384
#define NHEAD  8
#define DH     48
#define MROWS  (BB*NT)     // 32768
#define CHID   1536

// ---- scratch (static device arrays; no allocation allowed) ----------------
__device__ float g_xn [MROWS*CC];
__device__ float g_q  [MROWS*CC];
__device__ float g_kv [MROWS*2*CC];
__device__ float g_attn[BB*NHEAD*DH*DH];
__device__ float g_x2 [MROWS*CC];
__device__ float g_x3 [MROWS*CC];

__device__ __half g_xn_h[MROWS*CC];
__device__ __half g_sn_h[MROWS*CC];
__device__ __half g_ao_h[MROWS*CC];
__device__ __half g_h0_h[MROWS*CC];
__device__ __half g_h1_h[MROWS*CHID];

// weights, fp16, TRANSPOSED [N,K] layout (GEMM B operand)
__device__ __half g_wq_h [CC*CC];
__device__ __half g_wkv_h[2*CC*CC];
__device__ __half g_wpj_h[CC*CC];
__device__ __half g_wf1_h[CHID*CC];
__device__ __half g_wf2_h[CC*CHID];

// ============================ helpers ======================================
__device__ __forceinline__ uint32_t smem_u32(const void* p) {
    uint32_t a;
    asm("{ .reg .u64 t; cvta.to.shared.u64 t, %1; cvt.u32.u64 %0, t; }"
        : "=r"(a) : "l"(p));
    return a;
}

#define CP_ASYNC16(dst, src) \
    asm volatile("cp.async.cg.shared.global [%0], [%1], 16;" \
                 :: "r"(dst), "l"(src) : "memory")
#define CP_COMMIT()  asm volatile("cp.async.commit_group;" ::: "memory")
#define CP_WAIT0()   asm volatile("cp.async.wait_group 0;" ::: "memory")
#define CP_WAIT1()   asm volatile("cp.async.wait_group 1;" ::: "memory")

#define LDSM4(r, a) \
    asm volatile("ldmatrix.sync.aligned.m8n8.x4.shared.b16 {%0,%1,%2,%3}, [%4];" \
                 : "=r"((r)[0]), "=r"((r)[1]), "=r"((r)[2]), "=r"((r)[3]) : "r"(a))

#define MMA16816(d, a, b) \
    asm volatile("mma.sync.aligned.m16n8k16.row.col.f32.f16.f16.f32 " \
                 "{%0,%1,%2,%3}, {%4,%5,%6,%7}, {%8,%9}, {%0,%1,%2,%3};" \
                 : "+f"((d)[0]), "+f"((d)[1]), "+f"((d)[2]), "+f"((d)[3]) \
                 : "r"((a)[0]), "r"((a)[1]), "r"((a)[2]), "r"((a)[3]), \
                   "r"((b)[0]), "r"((b)[1]))

// ---------------------------------------------------------------------------
// Tiled weight transpose + fp16 convert: W[K,N] fp32 -> [N,K] fp16.
// ---------------------------------------------------------------------------
__global__ void wtrans_kernel(const float* __restrict__ W,
                              __half* __restrict__ O, int K, int N)
{
    __shared__ float t[32][33];
    int n0 = blockIdx.x * 32;
    int k0 = blockIdx.y * 32;
    int tx = threadIdx.x, ty = threadIdx.y;
#pragma unroll
    for (int r = ty; r < 32; r += 8)
        t[r][tx] = W[(size_t)(k0 + r) * N + n0 + tx];
    __syncthreads();
#pragma unroll
    for (int r = ty; r < 32; r += 8)
        O[(size_t)(n0 + r) * K + k0 + tx] = __float2half_rn(t[tx][r]);
}

// ---------------------------------------------------------------------------
// Fused depthwise 3x3 conv (+bias +residual) and LayerNorm.
// Block = 384 threads (channels) x 8 consecutive x-pixels (same y).
// Sliding 3x3 column window; LN reduction via smem transpose: v staged to
// vsh[8][384], then 8 warps each reduce one pixel (12 LDS + shuffles)
// instead of 160 shuffle ops on every thread.
// ---------------------------------------------------------------------------
__global__ void __launch_bounds__(384)
dwconv_ln_kernel(const float* __restrict__ x,
                 const float* __restrict__ w,
                 const float* __restrict__ cb,
                 const float* __restrict__ g,
                 const float* __restrict__ b,
                 float* __restrict__ rawOut,
                 float* __restrict__ normF,
                 __half* __restrict__ normH)
{
    int row0 = blockIdx.x * 8;
    int c    = threadIdx.x;
    int pix0 = row0 & (NT - 1);
    int y    = pix0 >> 6;
    int x0   = pix0 & 63;
    const float* xb = x + (size_t)(row0 - pix0) * CC + c;

    float wr[9];
#pragma unroll
    for (int t = 0; t < 9; t++) wr[t] = w[c * 9 + t];

    const bool y0ok = (y > 0);
    const bool y2ok = (y < HH - 1);

    float c0[3], c1[3], c2[3];

#define LOADC(xc, col) do {                                                   \
    int _xc = (xc);                                                           \
    bool _xok = (_xc >= 0) && (_xc < WW);                                     \
    (col)[0] = (_xok && y0ok) ? xb[(size_t)((y - 1) * WW + _xc) * CC] : 0.f;  \
    (col)[1] = (_xok)         ? xb[(size_t)( y      * WW + _xc) * CC] : 0.f;  \
    (col)[2] = (_xok && y2ok) ? xb[(size_t)((y + 1) * WW + _xc) * CC] : 0.f;  \
} while (0)

    LOADC(x0 - 1, c0);
    LOADC(x0,     c1);

    float bias = cb[c];
    float v[8];
#pragma unroll
    for (int p = 0; p < 8; p++) {
        LOADC(x0 + p + 1, c2);
        float a = bias
            + wr[0] * c0[0] + wr[1] * c1[0] + wr[2] * c2[0]
            + wr[3] * c0[1] + wr[4] * c1[1] + wr[5] * c2[1]
            + wr[6] * c0[2] + wr[7] * c1[2] + wr[8] * c2[2];
        v[p] = c1[1] + a;          // residual = center pixel value
        if (rawOut) rawOut[(size_t)(row0 + p) * CC + c] = v[p];
        c0[0] = c1[0]; c0[1] = c1[1]; c0[2] = c1[2];
        c1[0] = c2[0]; c1[1] = c2[1]; c1[2] = c2[2];
    }
#undef LOADC

    // LayerNorm via smem transpose: stage all v, 8 warps reduce 8 pixels.
    __shared__ float vsh[8][CC];
    __shared__ float mus[8], rsd[8];
    int wid = c >> 5, lane = c & 31;
#pragma unroll
    for (int p = 0; p < 8; p++) vsh[p][c] = v[p];
    __syncthreads();
    if (wid < 8) {                 // warp w reduces pixel w
        float s1 = 0.f, s2 = 0.f;
#pragma unroll
        for (int i = 0; i < 12; i++) {
            float t = vsh[wid][lane + 32 * i];
            s1 += t;
            s2 += t * t;
        }
#pragma unroll
        for (int o = 16; o > 0; o >>= 1) {
            s1 += __shfl_xor_sync(0xffffffffu, s1, o);
            s2 += __shfl_xor_sync(0xffffffffu, s2, o);
        }
        if (lane == 0) {
            float mu = s1 * (1.f / CC);
            mus[wid] = mu;
            rsd[wid] = rsqrtf(s2 * (1.f / CC) - mu * mu + 1e-5f);
        }
    }
    __syncthreads();
    float gg = g[c], bbv = b[c];
#pragma unroll
    for (int p = 0; p < 8; p++) {
        float o = (v[p] - mus[p]) * rsd[p] * gg + bbv;
        if (normF) normF[(size_t)(row0 + p) * CC + c] = o;
        normH[(size_t)(row0 + p) * CC + c] = __float2half_rn(o);
    }
}

// ---------------------------------------------------------------------------
// fp16 GEMM via mma.sync (R8-proven core, verbatim).  C[M,Nfull] = A @ W.
// A fp16 [M,KTOT]; B = W^T fp16 [Nfull,KTOT].
// 128x128 CTA tile, BK=64, double-buffered cp.async.
// Smem rows: 144B stride (conflict-free ldmatrix). 8 warps 4x2; 32x64/warp.
// EPI: 0 plain fp32; 1 +bias+residual fp32; 2 +bias+GELU -> fp16.
// ---------------------------------------------------------------------------
#define TILE_B   18432              // 128 rows * 144 bytes
#define STAGE_B  (2 * TILE_B)       // A, B = 36864
#define GSMEM_BYTES (2 * STAGE_B)   // 73728

template<int KTOT, int EPI>
__global__ void __launch_bounds__(256)
mma_gemm(const __half* __restrict__ Ah,
         const __half* __restrict__ Bh,
         const float* __restrict__ bias, const float* __restrict__ R,
         float* __restrict__ Cf, __half* __restrict__ Ch,
         int Nfull)
{
    extern __shared__ __align__(128) char smem[];
    const int tid  = threadIdx.x;
    const int lane = tid & 31;
    const int wid  = tid >> 5;
    const int wm   = wid & 3;
    const int wn   = wid >> 2;
    const int m0   = blockIdx.y * 128;
    const int n0   = blockIdx.x * 128;
    const uint32_t sbase = smem_u32(smem);

    // per-thread load slots: 2048 16B chunks (A 1024 + B 1024) / 256 = 8
    const __half* gp[8];
    uint32_t dso[8];
#pragma unroll
    for (int j = 0; j < 8; j++) {
        int idx  = j * 256 + tid;
        int tile = idx >> 10;           // 0=A 1=B
        int rid  = (idx >> 3) & 127;
        int seg  = idx & 7;
        const __half* base = (tile == 0) ? Ah : Bh;
        int rowg = ((tile == 0) ? m0 : n0) + rid;
        gp[j]  = base + (size_t)rowg * KTOT + seg * 8;
        dso[j] = (uint32_t)(tile * TILE_B + rid * 144 + seg * 16);
    }

    float acc[2][8][4];
#pragma unroll
    for (int mt = 0; mt < 2; mt++)
#pragma unroll
        for (int nt = 0; nt < 8; nt++)
#pragma unroll
            for (int q = 0; q < 4; q++) acc[mt][nt][q] = 0.f;

    constexpr int NC = KTOT / 64;

    {
        uint32_t sb = sbase;
#pragma unroll
        for (int j = 0; j < 8; j++) CP_ASYNC16(sb + dso[j], gp[j]);
        CP_COMMIT();
    }

    for (int c = 0; c < NC; c++) {
        const int s = c & 1;
        if (c + 1 < NC) {
            uint32_t sb = sbase + (1 - s) * STAGE_B;
            const int ko = (c + 1) * 64;
#pragma unroll
            for (int j = 0; j < 8; j++) CP_ASYNC16(sb + dso[j], gp[j] + ko);
            CP_COMMIT();
            CP_WAIT1();
        } else {
            CP_WAIT0();
        }
        __syncthreads();

        const uint32_t pa = sbase + s * STAGE_B;
#pragma unroll
        for (int ks = 0; ks < 4; ks++) {
            uint32_t af[2][4];
            const int arow = wm * 32 + (lane & 15);
            const int acol = ks * 16 + ((lane & 16) >> 1);
#pragma unroll
            for (int mt = 0; mt < 2; mt++) {
                uint32_t off = (uint32_t)((arow + mt * 16) * 144 + acol * 2);
                LDSM4(af[mt], pa + off);
            }
            uint32_t bf[8][2];
            const int brow = wn * 64 + ((lane & 16) >> 1) + (lane & 7);
            const int bcol = ks * 16 + (lane & 8);
#pragma unroll
            for (int p = 0; p < 4; p++) {
                uint32_t off = (uint32_t)((brow + p * 16) * 144 + bcol * 2);
                uint32_t t[4];
                LDSM4(t, pa + TILE_B + off);
                bf[2*p][0]   = t[0]; bf[2*p][1]   = t[1];
                bf[2*p+1][0] = t[2]; bf[2*p+1][1] = t[3];
            }
#pragma unroll
            for (int mt = 0; mt < 2; mt++)
#pragma unroll
                for (int nt = 0; nt < 8; nt++)
                    MMA16816(acc[mt][nt], af[mt], bf[nt]);
        }
        __syncthreads();
    }

    const int g  = lane >> 2;
    const int tg = (lane & 3) * 2;
#pragma unroll
    for (int mt = 0; mt < 2; mt++) {
#pragma unroll
        for (int nt = 0; nt < 8; nt++) {
            int colg = n0 + wn * 64 + nt * 8 + tg;
#pragma unroll
            for (int half_i = 0; half_i < 2; half_i++) {
                int rowg = m0 + wm * 32 + mt * 16 + g + half_i * 8;
                float v0 = acc[mt][nt][half_i * 2 + 0];
                float v1 = acc[mt][nt][half_i * 2 + 1];
                size_t off = (size_t)rowg * Nfull + colg;
                if (EPI == 0) {
                    float2 o = {v0, v1};
                    *(float2*)(Cf + off) = o;
                } else if (EPI == 1) {
                    v0 += bias[colg]     + R[off];
                    v1 += bias[colg + 1] + R[off + 1];
                    float2 o = {v0, v1};
                    *(float2*)(Cf + off) = o;
                } else {
                    v0 += bias[colg];
                    v1 += bias[colg + 1];
                    v0 = 0.5f * v0 * (1.f + erff(v0 * 0.70710678118654752f));
                    v1 = 0.5f * v1 * (1.f + erff(v1 * 0.70710678118654752f));
                    __half2 hp;
                    hp.x = __float2half_rn(v0);
                    hp.y = __float2half_rn(v1);
                    *(__half2*)(Ch + off) = hp;
                }
            }
        }
    }
}

// ---------------------------------------------------------------------------
// channel attention
// ---------------------------------------------------------------------------
__global__ void zero_kernel(float* __restrict__ p, int n)
{
    int i = blockIdx.x * blockDim.x + threadIdx.x;
    if (i < n) p[i] = 0.f;
}

__global__ void attn_logits_kernel(const float* __restrict__ kv,
                                   float* __restrict__ logits)
{
    int bh = blockIdx.x;
    int b = bh >> 3, head = bh & 7;
    int nstart = blockIdx.y * 512;

    __shared__ float4 ks4[64][12];
    __shared__ float4 vs4[64][12];

    int tid = threadIdx.x;               // 0..143
    int d4 = tid % 12;
    int e4 = tid / 12;
    float acc[4][4] = {{0.f,0.f,0.f,0.f},{0.f,0.f,0.f,0.f},
                       {0.f,0.f,0.f,0.f},{0.f,0.f,0.f,0.f}};

    const float* base = kv + (size_t)b * NT * (2 * CC) + head * DH;

    for (int nn = 0; nn < 512; nn += 64) {
        __syncthreads();
        for (int idx = tid; idx < 64 * 12; idx += 144) {
            int r = idx / 12, q = idx % 12;
            const float* rp = base + (size_t)(nstart + nn + r) * (2 * CC);
            ks4[r][q] = *(const float4*)(rp + q * 4);
            vs4[r][q] = *(const float4*)(rp + CC + q * 4);
        }
        __syncthreads();
#pragma unroll 4
        for (int r = 0; r < 64; r++) {
            float4 kk = ks4[r][d4];
            float4 vv = vs4[r][e4];
            acc[0][0] += kk.x*vv.x; acc[0][1] += kk.x*vv.y;
            acc[0][2] += kk.x*vv.z; acc[0][3] += kk.x*vv.w;
            acc[1][0] += kk.y*vv.x; acc[1][1] += kk.y*vv.y;
            acc[1][2] += kk.y*vv.z; acc[1][3] += kk.y*vv.w;
            acc[2][0] += kk.z*vv.x; acc[2][1] += kk.z*vv.y;
            acc[2][2] += kk.z*vv.z; acc[2][3] += kk.z*vv.w;
            acc[3][0] += kk.w*vv.x; acc[3][1] += kk.w*vv.y;
            acc[3][2] += kk.w*vv.z; acc[3][3] += kk.w*vv.w;
        }
    }
    int d0 = d4 * 4, e0 = e4 * 4;
#pragma unroll
    for (int i = 0; i < 4; i++)
#pragma unroll
        for (int j = 0; j < 4; j++)
            atomicAdd(&logits[((size_t)bh * DH + d0 + i) * DH + e0 + j], acc[i][j]);
}

__global__ void attn_softmax_kernel(float* __restrict__ logits)
{
    int gwarp = (int)((blockIdx.x * blockDim.x + threadIdx.x) >> 5);
    int lane = threadIdx.x & 31;
    if (gwarp >= BB * NHEAD * DH) return;
    float* L = logits + (size_t)gwarp * DH;
    const float scale = 0.14433756729740643f;   // 48^-0.5

    float a  = L[lane] * scale;
    float b2 = (lane < 16) ? L[32 + lane] * scale : -INFINITY;
    float m = fmaxf(a, b2);
#pragma unroll
    for (int o = 16; o > 0; o >>= 1) m = fmaxf(m, __shfl_xor_sync(0xffffffffu, m, o));
    float ea = expf(a - m);
    float eb = (lane < 16) ? expf(b2 - m) : 0.f;
    float s = ea + eb;
#pragma unroll
    for (int o = 16; o > 0; o >>= 1) s += __shfl_xor_sync(0xffffffffu, s, o);
    float inv = 1.f / s;
    L[lane] = ea * inv;
    if (lane < 16) L[32 + lane] = eb * inv;
}

__global__ void attn_apply_kernel(const float* __restrict__ q,
                                  const float* __restrict__ attn,
                                  __half* __restrict__ aoh)
{
    int row0 = blockIdx.x * 8;
    int c = threadIdx.x;                 // 0..383
    __shared__ float qs[8][CC];
#pragma unroll
    for (int r = 0; r < 8; r++) qs[r][c] = q[(size_t)(row0 + r) * CC + c];
    __syncthreads();

    int head = c / DH, dd = c - head * DH;
    int b = row0 >> 12;
    const float* arow = attn + ((size_t)((b * NHEAD + head) * DH + dd)) * DH;

    float acc[8] = {0.f,0.f,0.f,0.f,0.f,0.f,0.f,0.f};
#pragma unroll
    for (int e = 0; e < DH; e++) {
        float a = arow[e];
#pragma unroll
        for (int r = 0; r < 8; r++) acc[r] += a * qs[r][head * DH + e];
    }
#pragma unroll
    for (int r = 0; r < 8; r++)
        aoh[(size_t)(row0 + r) * CC + c] = __float2half_rn(acc[r]);
}

// ---------------------------------------------------------------------------
extern "C" void kernel_launch(void* const* d_in, const int* in_sizes, int n_in,
                              void* d_out, int out_size)
{
    const float* x      = (const float*)d_in[0];
    const float* src    = (const float*)d_in[1];
    const float* cpe0_w = (const float*)d_in[4];
    const float* cpe0_b = (const float*)d_in[5];
    const float* cpe1_w = (const float*)d_in[6];
    const float* cpe1_b = (const float*)d_in[7];
    const float* n1g    = (const float*)d_in[8];
    const float* n1b    = (const float*)d_in[9];
    const float* q_w    = (const float*)d_in[10];
    const float* kv_w   = (const float*)d_in[11];
    const float* pj_w   = (const float*)d_in[12];
    const float* pj_b   = (const float*)d_in[13];
    const float* n2g    = (const float*)d_in[14];
    const float* n2b    = (const float*)d_in[15];
    const float* f1w    = (const float*)d_in[16];
    const float* f1b    = (const float*)d_in[17];
    const float* f2w    = (const float*)d_in[18];
    const float* f2b    = (const float*)d_in[19];
    float* out = (float*)d_out;

    float *p_xn, *p_q, *p_kv, *p_attn, *p_x2, *p_x3;
    cudaGetSymbolAddress((void**)&p_xn,  g_xn);
    cudaGetSymbolAddress((void**)&p_q,   g_q);
    cudaGetSymbolAddress((void**)&p_kv,  g_kv);
    cudaGetSymbolAddress((void**)&p_attn,g_attn);
    cudaGetSymbolAddress((void**)&p_x2,  g_x2);
    cudaGetSymbolAddress((void**)&p_x3,  g_x3);

    __half *xnh,*snh,*aoh,*h0h,*h1h;
    __half *wqh,*wkvh,*wpjh,*wf1h,*wf2h;
    cudaGetSymbolAddress((void**)&xnh, g_xn_h);
    cudaGetSymbolAddress((void**)&snh, g_sn_h);
    cudaGetSymbolAddress((void**)&aoh, g_ao_h);
    cudaGetSymbolAddress((void**)&h0h, g_h0_h);
    cudaGetSymbolAddress((void**)&h1h, g_h1_h);
    cudaGetSymbolAddress((void**)&wqh, g_wq_h);
    cudaGetSymbolAddress((void**)&wkvh,g_wkv_h);
    cudaGetSymbolAddress((void**)&wpjh,g_wpj_h);
    cudaGetSymbolAddress((void**)&wf1h,g_wf1_h);
    cudaGetSymbolAddress((void**)&wf2h,g_wf2_h);

    cudaFuncSetAttribute(mma_gemm<384, 0>,  cudaFuncAttributeMaxDynamicSharedMemorySize, GSMEM_BYTES);
    cudaFuncSetAttribute(mma_gemm<384, 1>,  cudaFuncAttributeMaxDynamicSharedMemorySize, GSMEM_BYTES);
    cudaFuncSetAttribute(mma_gemm<384, 2>,  cudaFuncAttributeMaxDynamicSharedMemorySize, GSMEM_BYTES);
    cudaFuncSetAttribute(mma_gemm<1536, 1>, cudaFuncAttributeMaxDynamicSharedMemorySize, GSMEM_BYTES);

    dim3 tb(32, 8);

    // Launch order: index 5 (ncu -s 5 -c 1 slot) = dwconv_ln on src.
    // 0-2: weight transposes (q, kv, pj)
    wtrans_kernel<<<dim3(CC/32, CC/32), tb>>>(q_w, wqh, CC, CC);
    wtrans_kernel<<<dim3(2*CC/32, CC/32), tb>>>(kv_w, wkvh, CC, 2*CC);
    wtrans_kernel<<<dim3(CC/32, CC/32), tb>>>(pj_w, wpjh, CC, CC);

    // 3: fused CPE0+LN on x;  4: q projection;  5: fused CPE0+LN on src
    dwconv_ln_kernel<<<MROWS/8, CC>>>(x, cpe0_w, cpe0_b, n1g, n1b,
                                      nullptr, p_xn, xnh);
    mma_gemm<384, 0><<<dim3(CC/128, MROWS/128), 256, GSMEM_BYTES>>>(
        xnh, wqh, nullptr, nullptr, p_q, nullptr, CC);
    dwconv_ln_kernel<<<MROWS/8, CC>>>(src, cpe0_w, cpe0_b, n1g, n1b,
                                      nullptr, nullptr, snh);

    // 6: kv projection
    mma_gemm<384, 0><<<dim3(2*CC/128, MROWS/128), 256, GSMEM_BYTES>>>(
        snh, wkvh, nullptr, nullptr, p_kv, nullptr, 2*CC);

    // 7-10: channel attention
    zero_kernel<<<(BB*NHEAD*DH*DH + 255)/256, 256>>>(p_attn, BB*NHEAD*DH*DH);
    attn_logits_kernel<<<dim3(BB*NHEAD, 8), 144>>>(p_kv, p_attn);
    attn_softmax_kernel<<<(BB*NHEAD*DH + 7)/8, 256>>>(p_attn);
    attn_apply_kernel<<<MROWS/8, CC>>>(p_q, p_attn, aoh);

    // 11: proj + bias + residual(xn)
    mma_gemm<384, 1><<<dim3(CC/128, MROWS/128), 256, GSMEM_BYTES>>>(
        aoh, wpjh, pj_b, p_xn, p_x2, nullptr, CC);

    // 12: fused CPE1+LN (x3 fp32 conv result kept as fc2 residual)
    dwconv_ln_kernel<<<MROWS/8, CC>>>(p_x2, cpe1_w, cpe1_b, n2g, n2b,
                                      p_x3, nullptr, h0h);

    // 13-16: MLP
    wtrans_kernel<<<dim3(CHID/32, CC/32), tb>>>(f1w, wf1h, CC, CHID);
    wtrans_kernel<<<dim3(CC/32, CHID/32), tb>>>(f2w, wf2h, CHID, CC);
    mma_gemm<384, 2><<<dim3(CHID/128, MROWS/128), 256, GSMEM_BYTES>>>(
        h0h, wf1h, f1b, nullptr, nullptr, h1h, CHID);
    mma_gemm<1536, 1><<<dim3(CC/128, MROWS/128), 256, GSMEM_BYTES>>>(
        h1h, wf2h, f2b, p_x3, out, nullptr, CC);
}

// round 17
// speedup vs baseline: 1.5150x; 1.1856x over previous
#include <cuda_runtime.h>
#include <cuda_fp16.h>
#include <math.h>
#include <cstdint>

// ---------------------------------------------------------------------------
// ChannelBlock on GB300 (compute_103 base target):
// fp16 mma.sync GEMMs (R8-proven core) + float2 channel-pair dwconv+LN
// + float4-vectorized attention apply.
// Shapes: B=8, H=W=64, N=4096, C=384, heads=8, d=48, Ch=1536, M=B*N=32768
// ---------------------------------------------------------------------------

#define BB     8
#define HH     64
#define WW     64
#define NT     4096
#define CC     384
#define NHEAD  8
#define DH     48
#define MROWS  (BB*NT)     // 32768
#define CHID   1536

// ---- scratch (static device arrays; no allocation allowed) ----------------
__device__ float g_xn [MROWS*CC];
__device__ float g_q  [MROWS*CC];
__device__ float g_kv [MROWS*2*CC];
__device__ float g_attn[BB*NHEAD*DH*DH];
__device__ float g_x2 [MROWS*CC];
__device__ float g_x3 [MROWS*CC];

__device__ __half g_xn_h[MROWS*CC];
__device__ __half g_sn_h[MROWS*CC];
__device__ __half g_ao_h[MROWS*CC];
__device__ __half g_h0_h[MROWS*CC];
__device__ __half g_h1_h[MROWS*CHID];

// weights, fp16, TRANSPOSED [N,K] layout (GEMM B operand)
__device__ __half g_wq_h [CC*CC];
__device__ __half g_wkv_h[2*CC*CC];
__device__ __half g_wpj_h[CC*CC];
__device__ __half g_wf1_h[CHID*CC];
__device__ __half g_wf2_h[CC*CHID];

// ============================ helpers ======================================
__device__ __forceinline__ uint32_t smem_u32(const void* p) {
    uint32_t a;
    asm("{ .reg .u64 t; cvta.to.shared.u64 t, %1; cvt.u32.u64 %0, t; }"
        : "=r"(a) : "l"(p));
    return a;
}

#define CP_ASYNC16(dst, src) \
    asm volatile("cp.async.cg.shared.global [%0], [%1], 16;" \
                 :: "r"(dst), "l"(src) : "memory")
#define CP_COMMIT()  asm volatile("cp.async.commit_group;" ::: "memory")
#define CP_WAIT0()   asm volatile("cp.async.wait_group 0;" ::: "memory")
#define CP_WAIT1()   asm volatile("cp.async.wait_group 1;" ::: "memory")

#define LDSM4(r, a) \
    asm volatile("ldmatrix.sync.aligned.m8n8.x4.shared.b16 {%0,%1,%2,%3}, [%4];" \
                 : "=r"((r)[0]), "=r"((r)[1]), "=r"((r)[2]), "=r"((r)[3]) : "r"(a))

#define MMA16816(d, a, b) \
    asm volatile("mma.sync.aligned.m16n8k16.row.col.f32.f16.f16.f32 " \
                 "{%0,%1,%2,%3}, {%4,%5,%6,%7}, {%8,%9}, {%0,%1,%2,%3};" \
                 : "+f"((d)[0]), "+f"((d)[1]), "+f"((d)[2]), "+f"((d)[3]) \
                 : "r"((a)[0]), "r"((a)[1]), "r"((a)[2]), "r"((a)[3]), \
                   "r"((b)[0]), "r"((b)[1]))

// ---------------------------------------------------------------------------
// Tiled weight transpose + fp16 convert: W[K,N] fp32 -> [N,K] fp16.
// ---------------------------------------------------------------------------
__global__ void wtrans_kernel(const float* __restrict__ W,
                              __half* __restrict__ O, int K, int N)
{
    __shared__ float t[32][33];
    int n0 = blockIdx.x * 32;
    int k0 = blockIdx.y * 32;
    int tx = threadIdx.x, ty = threadIdx.y;
#pragma unroll
    for (int r = ty; r < 32; r += 8)
        t[r][tx] = W[(size_t)(k0 + r) * N + n0 + tx];
    __syncthreads();
#pragma unroll
    for (int r = ty; r < 32; r += 8)
        O[(size_t)(n0 + r) * K + k0 + tx] = __float2half_rn(t[tx][r]);
}

// ---------------------------------------------------------------------------
// Fused depthwise 3x3 conv (+bias +residual) and LayerNorm.
// Block = 192 threads (channel PAIRS, float2) x 8 consecutive x-pixels.
// Sliding 3x3 float2 column window; LN via smem transpose (6 warps cover
// 8 pixel-reductions).
// ---------------------------------------------------------------------------
__global__ void __launch_bounds__(192)
dwconv_ln_kernel(const float* __restrict__ x,
                 const float* __restrict__ w,
                 const float* __restrict__ cb,
                 const float* __restrict__ g,
                 const float* __restrict__ b,
                 float* __restrict__ rawOut,
                 float* __restrict__ normF,
                 __half* __restrict__ normH)
{
    int row0 = blockIdx.x * 8;
    int cp   = threadIdx.x;            // channel pair 0..191 -> channels 2cp,2cp+1
    int pix0 = row0 & (NT - 1);
    int y    = pix0 >> 6;
    int x0   = pix0 & 63;
    const float2* xb = (const float2*)(x + (size_t)(row0 - pix0) * CC) + cp;

    float2 wr[9];
    {
        const float* w0 = w + (2 * cp) * 9;
        const float* w1 = w0 + 9;
#pragma unroll
        for (int t = 0; t < 9; t++) { wr[t].x = w0[t]; wr[t].y = w1[t]; }
    }

    const bool y0ok = (y > 0);
    const bool y2ok = (y < HH - 1);

    float2 c0[3], c1[3], c2[3];
    const float2 z2 = {0.f, 0.f};

#define LOADC(xc, col) do {                                                    \
    int _xc = (xc);                                                            \
    bool _xok = (_xc >= 0) && (_xc < WW);                                      \
    (col)[0] = (_xok && y0ok) ? xb[(size_t)((y - 1) * WW + _xc) * (CC/2)] : z2;\
    (col)[1] = (_xok)         ? xb[(size_t)( y      * WW + _xc) * (CC/2)] : z2;\
    (col)[2] = (_xok && y2ok) ? xb[(size_t)((y + 1) * WW + _xc) * (CC/2)] : z2;\
} while (0)

    LOADC(x0 - 1, c0);
    LOADC(x0,     c1);

    float2 bias = *(const float2*)(cb + 2 * cp);
    float2 v[8];
#pragma unroll
    for (int p = 0; p < 8; p++) {
        LOADC(x0 + p + 1, c2);
        float ax = bias.x, ay = bias.y;
#pragma unroll
        for (int k = 0; k < 3; k++) {
            ax += wr[k*3+0].x * c0[k].x + wr[k*3+1].x * c1[k].x + wr[k*3+2].x * c2[k].x;
            ay += wr[k*3+0].y * c0[k].y + wr[k*3+1].y * c1[k].y + wr[k*3+2].y * c2[k].y;
        }
        v[p].x = c1[1].x + ax;         // residual = center pixel value
        v[p].y = c1[1].y + ay;
        if (rawOut) *(float2*)(rawOut + (size_t)(row0 + p) * CC + 2 * cp) = v[p];
        c0[0] = c1[0]; c0[1] = c1[1]; c0[2] = c1[2];
        c1[0] = c2[0]; c1[1] = c2[1]; c1[2] = c2[2];
    }
#undef LOADC

    // LayerNorm via smem transpose: 6 warps cover 8 pixels.
    __shared__ float2 vsh[8][192];
    __shared__ float mus[8], rsd[8];
    int wid = cp >> 5, lane = cp & 31;
#pragma unroll
    for (int p = 0; p < 8; p++) vsh[p][cp] = v[p];
    __syncthreads();
    for (int p = wid; p < 8; p += 6) {
        float s1 = 0.f, s2 = 0.f;
#pragma unroll
        for (int i = 0; i < 6; i++) {
            float2 t = vsh[p][lane + 32 * i];
            s1 += t.x + t.y;
            s2 += t.x * t.x + t.y * t.y;
        }
#pragma unroll
        for (int o = 16; o > 0; o >>= 1) {
            s1 += __shfl_xor_sync(0xffffffffu, s1, o);
            s2 += __shfl_xor_sync(0xffffffffu, s2, o);
        }
        if (lane == 0) {
            float mu = s1 * (1.f / CC);
            mus[p] = mu;
            rsd[p] = rsqrtf(s2 * (1.f / CC) - mu * mu + 1e-5f);
        }
    }
    __syncthreads();
    float2 gg = *(const float2*)(g + 2 * cp);
    float2 bv = *(const float2*)(b + 2 * cp);
#pragma unroll
    for (int p = 0; p < 8; p++) {
        float ox = (v[p].x - mus[p]) * rsd[p] * gg.x + bv.x;
        float oy = (v[p].y - mus[p]) * rsd[p] * gg.y + bv.y;
        size_t off = (size_t)(row0 + p) * CC + 2 * cp;
        if (normF) { float2 o = {ox, oy}; *(float2*)(normF + off) = o; }
        __half2 hp;
        hp.x = __float2half_rn(ox);
        hp.y = __float2half_rn(oy);
        *(__half2*)(normH + off) = hp;
    }
}

// ---------------------------------------------------------------------------
// fp16 GEMM via mma.sync (R8-proven core, verbatim).  C[M,Nfull] = A @ W.
// ---------------------------------------------------------------------------
#define TILE_B   18432              // 128 rows * 144 bytes
#define STAGE_B  (2 * TILE_B)       // A, B = 36864
#define GSMEM_BYTES (2 * STAGE_B)   // 73728

template<int KTOT, int EPI>
__global__ void __launch_bounds__(256)
mma_gemm(const __half* __restrict__ Ah,
         const __half* __restrict__ Bh,
         const float* __restrict__ bias, const float* __restrict__ R,
         float* __restrict__ Cf, __half* __restrict__ Ch,
         int Nfull)
{
    extern __shared__ __align__(128) char smem[];
    const int tid  = threadIdx.x;
    const int lane = tid & 31;
    const int wid  = tid >> 5;
    const int wm   = wid & 3;
    const int wn   = wid >> 2;
    const int m0   = blockIdx.y * 128;
    const int n0   = blockIdx.x * 128;
    const uint32_t sbase = smem_u32(smem);

    const __half* gp[8];
    uint32_t dso[8];
#pragma unroll
    for (int j = 0; j < 8; j++) {
        int idx  = j * 256 + tid;
        int tile = idx >> 10;           // 0=A 1=B
        int rid  = (idx >> 3) & 127;
        int seg  = idx & 7;
        const __half* base = (tile == 0) ? Ah : Bh;
        int rowg = ((tile == 0) ? m0 : n0) + rid;
        gp[j]  = base + (size_t)rowg * KTOT + seg * 8;
        dso[j] = (uint32_t)(tile * TILE_B + rid * 144 + seg * 16);
    }

    float acc[2][8][4];
#pragma unroll
    for (int mt = 0; mt < 2; mt++)
#pragma unroll
        for (int nt = 0; nt < 8; nt++)
#pragma unroll
            for (int q = 0; q < 4; q++) acc[mt][nt][q] = 0.f;

    constexpr int NC = KTOT / 64;

    {
        uint32_t sb = sbase;
#pragma unroll
        for (int j = 0; j < 8; j++) CP_ASYNC16(sb + dso[j], gp[j]);
        CP_COMMIT();
    }

    for (int c = 0; c < NC; c++) {
        const int s = c & 1;
        if (c + 1 < NC) {
            uint32_t sb = sbase + (1 - s) * STAGE_B;
            const int ko = (c + 1) * 64;
#pragma unroll
            for (int j = 0; j < 8; j++) CP_ASYNC16(sb + dso[j], gp[j] + ko);
            CP_COMMIT();
            CP_WAIT1();
        } else {
            CP_WAIT0();
        }
        __syncthreads();

        const uint32_t pa = sbase + s * STAGE_B;
#pragma unroll
        for (int ks = 0; ks < 4; ks++) {
            uint32_t af[2][4];
            const int arow = wm * 32 + (lane & 15);
            const int acol = ks * 16 + ((lane & 16) >> 1);
#pragma unroll
            for (int mt = 0; mt < 2; mt++) {
                uint32_t off = (uint32_t)((arow + mt * 16) * 144 + acol * 2);
                LDSM4(af[mt], pa + off);
            }
            uint32_t bf[8][2];
            const int brow = wn * 64 + ((lane & 16) >> 1) + (lane & 7);
            const int bcol = ks * 16 + (lane & 8);
#pragma unroll
            for (int p = 0; p < 4; p++) {
                uint32_t off = (uint32_t)((brow + p * 16) * 144 + bcol * 2);
                uint32_t t[4];
                LDSM4(t, pa + TILE_B + off);
                bf[2*p][0]   = t[0]; bf[2*p][1]   = t[1];
                bf[2*p+1][0] = t[2]; bf[2*p+1][1] = t[3];
            }
#pragma unroll
            for (int mt = 0; mt < 2; mt++)
#pragma unroll
                for (int nt = 0; nt < 8; nt++)
                    MMA16816(acc[mt][nt], af[mt], bf[nt]);
        }
        __syncthreads();
    }

    const int g  = lane >> 2;
    const int tg = (lane & 3) * 2;
#pragma unroll
    for (int mt = 0; mt < 2; mt++) {
#pragma unroll
        for (int nt = 0; nt < 8; nt++) {
            int colg = n0 + wn * 64 + nt * 8 + tg;
#pragma unroll
            for (int half_i = 0; half_i < 2; half_i++) {
                int rowg = m0 + wm * 32 + mt * 16 + g + half_i * 8;
                float v0 = acc[mt][nt][half_i * 2 + 0];
                float v1 = acc[mt][nt][half_i * 2 + 1];
                size_t off = (size_t)rowg * Nfull + colg;
                if (EPI == 0) {
                    float2 o = {v0, v1};
                    *(float2*)(Cf + off) = o;
                } else if (EPI == 1) {
                    v0 += bias[colg]     + R[off];
                    v1 += bias[colg + 1] + R[off + 1];
                    float2 o = {v0, v1};
                    *(float2*)(Cf + off) = o;
                } else {
                    v0 += bias[colg];
                    v1 += bias[colg + 1];
                    v0 = 0.5f * v0 * (1.f + erff(v0 * 0.70710678118654752f));
                    v1 = 0.5f * v1 * (1.f + erff(v1 * 0.70710678118654752f));
                    __half2 hp;
                    hp.x = __float2half_rn(v0);
                    hp.y = __float2half_rn(v1);
                    *(__half2*)(Ch + off) = hp;
                }
            }
        }
    }
}

// ---------------------------------------------------------------------------
// channel attention
// ---------------------------------------------------------------------------
__global__ void zero_kernel(float* __restrict__ p, int n)
{
    int i = blockIdx.x * blockDim.x + threadIdx.x;
    if (i < n) p[i] = 0.f;
}

__global__ void attn_logits_kernel(const float* __restrict__ kv,
                                   float* __restrict__ logits)
{
    int bh = blockIdx.x;
    int b = bh >> 3, head = bh & 7;
    int nstart = blockIdx.y * 512;

    __shared__ float4 ks4[64][12];
    __shared__ float4 vs4[64][12];

    int tid = threadIdx.x;               // 0..143
    int d4 = tid % 12;
    int e4 = tid / 12;
    float acc[4][4] = {{0.f,0.f,0.f,0.f},{0.f,0.f,0.f,0.f},
                       {0.f,0.f,0.f,0.f},{0.f,0.f,0.f,0.f}};

    const float* base = kv + (size_t)b * NT * (2 * CC) + head * DH;

    for (int nn = 0; nn < 512; nn += 64) {
        __syncthreads();
        for (int idx = tid; idx < 64 * 12; idx += 144) {
            int r = idx / 12, q = idx % 12;
            const float* rp = base + (size_t)(nstart + nn + r) * (2 * CC);
            ks4[r][q] = *(const float4*)(rp + q * 4);
            vs4[r][q] = *(const float4*)(rp + CC + q * 4);
        }
        __syncthreads();
#pragma unroll 4
        for (int r = 0; r < 64; r++) {
            float4 kk = ks4[r][d4];
            float4 vv = vs4[r][e4];
            acc[0][0] += kk.x*vv.x; acc[0][1] += kk.x*vv.y;
            acc[0][2] += kk.x*vv.z; acc[0][3] += kk.x*vv.w;
            acc[1][0] += kk.y*vv.x; acc[1][1] += kk.y*vv.y;
            acc[1][2] += kk.y*vv.z; acc[1][3] += kk.y*vv.w;
            acc[2][0] += kk.z*vv.x; acc[2][1] += kk.z*vv.y;
            acc[2][2] += kk.z*vv.z; acc[2][3] += kk.z*vv.w;
            acc[3][0] += kk.w*vv.x; acc[3][1] += kk.w*vv.y;
            acc[3][2] += kk.w*vv.z; acc[3][3] += kk.w*vv.w;
        }
    }
    int d0 = d4 * 4, e0 = e4 * 4;
#pragma unroll
    for (int i = 0; i < 4; i++)
#pragma unroll
        for (int j = 0; j < 4; j++)
            atomicAdd(&logits[((size_t)bh * DH + d0 + i) * DH + e0 + j], acc[i][j]);
}

__global__ void attn_softmax_kernel(float* __restrict__ logits)
{
    int gwarp = (int)((blockIdx.x * blockDim.x + threadIdx.x) >> 5);
    int lane = threadIdx.x & 31;
    if (gwarp >= BB * NHEAD * DH) return;
    float* L = logits + (size_t)gwarp * DH;
    const float scale = 0.14433756729740643f;   // 48^-0.5

    float a  = L[lane] * scale;
    float b2 = (lane < 16) ? L[32 + lane] * scale : -INFINITY;
    float m = fmaxf(a, b2);
#pragma unroll
    for (int o = 16; o > 0; o >>= 1) m = fmaxf(m, __shfl_xor_sync(0xffffffffu, m, o));
    float ea = expf(a - m);
    float eb = (lane < 16) ? expf(b2 - m) : 0.f;
    float s = ea + eb;
#pragma unroll
    for (int o = 16; o > 0; o >>= 1) s += __shfl_xor_sync(0xffffffffu, s, o);
    float inv = 1.f / s;
    L[lane] = ea * inv;
    if (lane < 16) L[32 + lane] = eb * inv;
}

__global__ void attn_apply_kernel(const float* __restrict__ q,
                                  const float* __restrict__ attn,
                                  __half* __restrict__ aoh)
{
    int row0 = blockIdx.x * 8;
    int c = threadIdx.x;                 // 0..383
    __shared__ float qs[8][CC];
#pragma unroll
    for (int r = 0; r < 8; r++) qs[r][c] = q[(size_t)(row0 + r) * CC + c];
    __syncthreads();

    int head = c / DH, dd = c - head * DH;
    int b = row0 >> 12;
    const float4* a4 = (const float4*)(attn +
        ((size_t)((b * NHEAD + head) * DH + dd)) * DH);   // 48 floats = 12 float4

    float acc[8] = {0.f,0.f,0.f,0.f,0.f,0.f,0.f,0.f};
    const int qbase = head * DH;
#pragma unroll
    for (int e4 = 0; e4 < 12; e4++) {
        float4 a = a4[e4];
#pragma unroll
        for (int r = 0; r < 8; r++) {
            float4 qv = *(const float4*)&qs[r][qbase + e4 * 4];
            acc[r] += a.x * qv.x + a.y * qv.y + a.z * qv.z + a.w * qv.w;
        }
    }
#pragma unroll
    for (int r = 0; r < 8; r++)
        aoh[(size_t)(row0 + r) * CC + c] = __float2half_rn(acc[r]);
}

// ---------------------------------------------------------------------------
extern "C" void kernel_launch(void* const* d_in, const int* in_sizes, int n_in,
                              void* d_out, int out_size)
{
    const float* x      = (const float*)d_in[0];
    const float* src    = (const float*)d_in[1];
    const float* cpe0_w = (const float*)d_in[4];
    const float* cpe0_b = (const float*)d_in[5];
    const float* cpe1_w = (const float*)d_in[6];
    const float* cpe1_b = (const float*)d_in[7];
    const float* n1g    = (const float*)d_in[8];
    const float* n1b    = (const float*)d_in[9];
    const float* q_w    = (const float*)d_in[10];
    const float* kv_w   = (const float*)d_in[11];
    const float* pj_w   = (const float*)d_in[12];
    const float* pj_b   = (const float*)d_in[13];
    const float* n2g    = (const float*)d_in[14];
    const float* n2b    = (const float*)d_in[15];
    const float* f1w    = (const float*)d_in[16];
    const float* f1b    = (const float*)d_in[17];
    const float* f2w    = (const float*)d_in[18];
    const float* f2b    = (const float*)d_in[19];
    float* out = (float*)d_out;

    float *p_xn, *p_q, *p_kv, *p_attn, *p_x2, *p_x3;
    cudaGetSymbolAddress((void**)&p_xn,  g_xn);
    cudaGetSymbolAddress((void**)&p_q,   g_q);
    cudaGetSymbolAddress((void**)&p_kv,  g_kv);
    cudaGetSymbolAddress((void**)&p_attn,g_attn);
    cudaGetSymbolAddress((void**)&p_x2,  g_x2);
    cudaGetSymbolAddress((void**)&p_x3,  g_x3);

    __half *xnh,*snh,*aoh,*h0h,*h1h;
    __half *wqh,*wkvh,*wpjh,*wf1h,*wf2h;
    cudaGetSymbolAddress((void**)&xnh, g_xn_h);
    cudaGetSymbolAddress((void**)&snh, g_sn_h);
    cudaGetSymbolAddress((void**)&aoh, g_ao_h);
    cudaGetSymbolAddress((void**)&h0h, g_h0_h);
    cudaGetSymbolAddress((void**)&h1h, g_h1_h);
    cudaGetSymbolAddress((void**)&wqh, g_wq_h);
    cudaGetSymbolAddress((void**)&wkvh,g_wkv_h);
    cudaGetSymbolAddress((void**)&wpjh,g_wpj_h);
    cudaGetSymbolAddress((void**)&wf1h,g_wf1_h);
    cudaGetSymbolAddress((void**)&wf2h,g_wf2_h);

    cudaFuncSetAttribute(mma_gemm<384, 0>,  cudaFuncAttributeMaxDynamicSharedMemorySize, GSMEM_BYTES);
    cudaFuncSetAttribute(mma_gemm<384, 1>,  cudaFuncAttributeMaxDynamicSharedMemorySize, GSMEM_BYTES);
    cudaFuncSetAttribute(mma_gemm<384, 2>,  cudaFuncAttributeMaxDynamicSharedMemorySize, GSMEM_BYTES);
    cudaFuncSetAttribute(mma_gemm<1536, 1>, cudaFuncAttributeMaxDynamicSharedMemorySize, GSMEM_BYTES);

    dim3 tb(32, 8);

    // Launch order: index 5 (ncu -s 5 -c 1 slot) = dwconv_ln on src.
    // 0-2: weight transposes (q, kv, pj)
    wtrans_kernel<<<dim3(CC/32, CC/32), tb>>>(q_w, wqh, CC, CC);
    wtrans_kernel<<<dim3(2*CC/32, CC/32), tb>>>(kv_w, wkvh, CC, 2*CC);
    wtrans_kernel<<<dim3(CC/32, CC/32), tb>>>(pj_w, wpjh, CC, CC);

    // 3: fused CPE0+LN on x;  4: q projection;  5: fused CPE0+LN on src
    dwconv_ln_kernel<<<MROWS/8, 192>>>(x, cpe0_w, cpe0_b, n1g, n1b,
                                       nullptr, p_xn, xnh);
    mma_gemm<384, 0><<<dim3(CC/128, MROWS/128), 256, GSMEM_BYTES>>>(
        xnh, wqh, nullptr, nullptr, p_q, nullptr, CC);
    dwconv_ln_kernel<<<MROWS/8, 192>>>(src, cpe0_w, cpe0_b, n1g, n1b,
                                       nullptr, nullptr, snh);

    // 6: kv projection
    mma_gemm<384, 0><<<dim3(2*CC/128, MROWS/128), 256, GSMEM_BYTES>>>(
        snh, wkvh, nullptr, nullptr, p_kv, nullptr, 2*CC);

    // 7-10: channel attention
    zero_kernel<<<(BB*NHEAD*DH*DH + 255)/256, 256>>>(p_attn, BB*NHEAD*DH*DH);
    attn_logits_kernel<<<dim3(BB*NHEAD, 8), 144>>>(p_kv, p_attn);
    attn_softmax_kernel<<<(BB*NHEAD*DH + 7)/8, 256>>>(p_attn);
    attn_apply_kernel<<<MROWS/8, CC>>>(p_q, p_attn, aoh);

    // 11: proj + bias + residual(xn)
    mma_gemm<384, 1><<<dim3(CC/128, MROWS/128), 256, GSMEM_BYTES>>>(
        aoh, wpjh, pj_b, p_xn, p_x2, nullptr, CC);

    // 12: fused CPE1+LN (x3 fp32 conv result kept as fc2 residual)
    dwconv_ln_kernel<<<MROWS/8, 192>>>(p_x2, cpe1_w, cpe1_b, n2g, n2b,
                                       p_x3, nullptr, h0h);

    // 13-16: MLP
    wtrans_kernel<<<dim3(CHID/32, CC/32), tb>>>(f1w, wf1h, CC, CHID);
    wtrans_kernel<<<dim3(CC/32, CHID/32), tb>>>(f2w, wf2h, CHID, CC);
    mma_gemm<384, 2><<<dim3(CHID/128, MROWS/128), 256, GSMEM_BYTES>>>(
        h0h, wf1h, f1b, nullptr, nullptr, h1h, CHID);
    mma_gemm<1536, 1><<<dim3(CC/128, MROWS/128), 256, GSMEM_BYTES>>>(
        h1h, wf2h, f2b, p_x3, out, nullptr, CC);
}